// round 14
// baseline (speedup 1.0000x reference)
#include <cuda_runtime.h>
#include <cuda_bf16.h>
#include <cstdint>

// Problem constants
#define D_MODEL 1024
#define D_INNER 2048
#define D_STATE 16
#define D_CONV  4
#define DT_RANK 64
#define BATCH   2
#define SEQLEN  1024
#define NROWS   (BATCH * SEQLEN)          // 2048 "M" rows
#define NDBL    (DT_RANK + 2 * D_STATE)   // 96
#define NCHUNK  32
#define CLEN    32                        // SEQLEN / NCHUNK

// ---------------- scratch (device globals; no allocation) ----------------
__device__ float g_xz[(size_t)NROWS * 2 * D_INNER];     // (2048, 4096) x|z
__device__ float g_xc[(size_t)NROWS * D_INNER];         // (2048, 2048) conv+silu
__device__ float g_xdbl[(size_t)NROWS * NDBL];          // (2048, 96) dt|B|C
__device__ float g_gate[BATCH * NDBL];                  // (2, 96)
__device__ float g_delta[(size_t)NROWS * D_INNER];      // (2048, 2048)

// packed tf32 operand tiles: [tileM(or N)/128][K/32][4096 words]
__device__ uint32_t g_hid_p[(size_t)NROWS * D_MODEL];            // A of G1
__device__ uint32_t g_w1_p[(size_t)2 * D_INNER * D_MODEL];       // B of G1
__device__ uint32_t g_xc_p[(size_t)NROWS * D_INNER];             // A of G2
__device__ uint32_t g_w2_p[(size_t)128 * D_INNER];               // B of G2 (pad 96->128)
__device__ uint32_t g_dt_p[(size_t)NROWS * DT_RANK];             // A of G3
__device__ uint32_t g_w3_p[(size_t)D_INNER * DT_RANK];           // B of G3
__device__ uint32_t g_y_p[(size_t)NROWS * D_INNER];              // A of G4
__device__ uint32_t g_w4_p[(size_t)D_MODEL * D_INNER];           // B of G4

// ---------------- helpers ----------------
__device__ __forceinline__ uint32_t f2tf32(float x) {
    uint32_t r;
    asm("cvt.rna.tf32.f32 %0, %1;" : "=r"(r) : "f"(x));
    return r;
}

__device__ __forceinline__ uint32_t smem_u32(const void* p) {
    uint32_t a;
    asm("{ .reg .u64 t; cvta.to.shared.u64 t, %1; cvt.u32.u64 %0, t; }"
        : "=r"(a) : "l"(p));
    return a;
}

__device__ __forceinline__ void mma_tf32(float c[4], const uint32_t a[4],
                                         const uint32_t b[2]) {
    asm volatile(
        "mma.sync.aligned.m16n8k8.row.col.f32.tf32.tf32.f32 "
        "{%0,%1,%2,%3}, {%4,%5,%6,%7}, {%8,%9}, {%0,%1,%2,%3};"
        : "+f"(c[0]), "+f"(c[1]), "+f"(c[2]), "+f"(c[3])
        : "r"(a[0]), "r"(a[1]), "r"(a[2]), "r"(a[3]), "r"(b[0]), "r"(b[1]));
}

#define CP16(dst, src) \
    asm volatile("cp.async.cg.shared.global [%0], [%1], 16;" \
                 :: "r"(dst), "l"(src) : "memory")

// fragment-packed word index within a 128x32 A tile (4096 words)
__device__ __forceinline__ int inner_a(int m, int k) {
    return ((m >> 4) * 4 + (k >> 3)) * 128 + (m & 7) * 16 + (k & 3) * 4 +
           ((k >> 2) & 1) * 2 + ((m >> 3) & 1);
}

// ---------------- coalesced pack kernels (smem-inverse; block = one tile) ---
__global__ __launch_bounds__(256) void pack_a_t(const float* __restrict__ src,
                                                uint32_t* __restrict__ dst, int K)
{
    __shared__ float s[128][33];
    const int tid = threadIdx.x;
    const int k0 = blockIdx.x * 32;
    const int row0 = blockIdx.y * 128;
    const int r = tid >> 1;
    const int cb = (tid & 1) * 16;
    const float* sp = src + (size_t)(row0 + r) * K + k0 + cb;
#pragma unroll
    for (int p = 0; p < 4; p++) {
        float4 v = *(const float4*)(sp + p * 4);
        s[r][cb + p * 4 + 0] = v.x; s[r][cb + p * 4 + 1] = v.y;
        s[r][cb + p * 4 + 2] = v.z; s[r][cb + p * 4 + 3] = v.w;
    }
    __syncthreads();
    uint32_t* dp = dst + ((size_t)blockIdx.y * gridDim.x + blockIdx.x) * 4096 + tid * 16;
#pragma unroll
    for (int q = 0; q < 4; q++) {
        uint4 o;
        uint32_t* po = (uint32_t*)&o;
#pragma unroll
        for (int w = 0; w < 4; w++) {
            int g = tid * 16 + q * 4 + w;
            int f = g >> 7, i = g & 127;
            int m = ((f >> 2) << 4) | ((i & 1) << 3) | (i >> 4);
            int k = ((f & 3) << 3) | (((i >> 1) & 1) << 2) | ((i >> 2) & 3);
            po[w] = f2tf32(s[m][k]);
        }
        *(uint4*)(dp + q * 4) = o;
    }
}

__global__ __launch_bounds__(256) void pack_b_t(const float* __restrict__ src,
                                                uint32_t* __restrict__ dst,
                                                int N, int K)
{
    __shared__ float s[128][33];
    const int tid = threadIdx.x;
    const int k0 = blockIdx.x * 32;
    const int n0 = blockIdx.y * 128;
    const int r = tid >> 1;
    const int cb = (tid & 1) * 16;
    const int gn = n0 + r;
    const float* sp = src + (size_t)gn * K + k0 + cb;
#pragma unroll
    for (int p = 0; p < 4; p++) {
        float4 v = (gn < N) ? *(const float4*)(sp + p * 4)
                            : make_float4(0.f, 0.f, 0.f, 0.f);
        s[r][cb + p * 4 + 0] = v.x; s[r][cb + p * 4 + 1] = v.y;
        s[r][cb + p * 4 + 2] = v.z; s[r][cb + p * 4 + 3] = v.w;
    }
    __syncthreads();
    uint32_t* dp = dst + ((size_t)blockIdx.y * gridDim.x + blockIdx.x) * 4096 + tid * 16;
#pragma unroll
    for (int q = 0; q < 4; q++) {
        uint4 o;
        uint32_t* po = (uint32_t*)&o;
#pragma unroll
        for (int w = 0; w < 4; w++) {
            int g = tid * 16 + q * 4 + w;
            int f = g >> 6, i = g & 63;
            int n = ((f >> 2) << 3) | (i >> 3);
            int k = ((f & 3) << 3) | ((i & 1) << 2) | ((i >> 1) & 3);
            po[w] = f2tf32(s[n][k]);
        }
        *(uint4*)(dp + q * 4) = o;
    }
}

// ---------------- 3-stage pipelined tensor-core tf32 GEMM ----------------
__global__ __launch_bounds__(128)
void gemm_mma_p(const uint32_t* __restrict__ Ap,
                const uint32_t* __restrict__ Bp,
                float* __restrict__ C, int ldc,
                int nKtiles, int ktCnt, int N,
                const float* __restrict__ bias, int act, int atomic)
{
    extern __shared__ uint32_t smem[];   // 3 * 8192 words = 96 KB

    const int tid = threadIdx.x;
    const int wid = tid >> 5;
    const int lane = tid & 31;
    const int warp_m = wid >> 1;
    const int warp_n = wid & 1;
    const int ktBeg = blockIdx.z * ktCnt;

    const uint32_t* gA = Ap + ((size_t)blockIdx.y * nKtiles + ktBeg) * 4096;
    const uint32_t* gB = Bp + ((size_t)blockIdx.x * nKtiles + ktBeg) * 4096;
    const uint32_t sbase = smem_u32(smem);

    float acc[4][8][4];
#pragma unroll
    for (int mi = 0; mi < 4; mi++)
#pragma unroll
        for (int ni = 0; ni < 8; ni++)
#pragma unroll
            for (int e = 0; e < 4; e++) acc[mi][ni][e] = 0.f;

#define ISSUE_STAGE(s) do { \
    int _buf = (s) % 3; \
    uint32_t _d = sbase + _buf * 32768 + tid * 16; \
    const char* _sA = (const char*)(gA + (size_t)(s) * 4096) + tid * 16; \
    const char* _sB = (const char*)(gB + (size_t)(s) * 4096) + tid * 16; \
    _Pragma("unroll") \
    for (int _i = 0; _i < 8; _i++) { \
        CP16(_d + _i * 2048, _sA + _i * 2048); \
        CP16(_d + 16384 + _i * 2048, _sB + _i * 2048); \
    } \
    asm volatile("cp.async.commit_group;" ::: "memory"); \
} while (0)

    ISSUE_STAGE(0);
    ISSUE_STAGE(1);                       // ktCnt >= 2 for all callers
    for (int s = 0; s < ktCnt; s++) {
        if (s + 1 < ktCnt) {
            asm volatile("cp.async.wait_group 1;" ::: "memory");
        } else {
            asm volatile("cp.async.wait_group 0;" ::: "memory");
        }
        __syncthreads();

        const uint32_t* sA = smem + (s % 3) * 8192;
        const uint32_t* sB = sA + 4096;
#pragma unroll
        for (int kc = 0; kc < 4; kc++) {
            uint4 af[4];
            uint2 bf[8];
#pragma unroll
            for (int mi = 0; mi < 4; mi++)
                af[mi] = *(const uint4*)&sA[((warp_m * 4 + mi) * 4 + kc) * 128 + lane * 4];
#pragma unroll
            for (int ni = 0; ni < 8; ni++)
                bf[ni] = *(const uint2*)&sB[((warp_n * 8 + ni) * 4 + kc) * 64 + lane * 2];
#pragma unroll
            for (int mi = 0; mi < 4; mi++)
#pragma unroll
                for (int ni = 0; ni < 8; ni++)
                    mma_tf32(acc[mi][ni], (const uint32_t*)&af[mi],
                             (const uint32_t*)&bf[ni]);
        }
        if (s + 2 < ktCnt) ISSUE_STAGE(s + 2);
    }
#undef ISSUE_STAGE

    const int r_lo = blockIdx.y * 128 + warp_m * 64 + (lane >> 2);
    const int c_lo = blockIdx.x * 128 + warp_n * 64 + (lane & 3) * 2;
    if (atomic) {
#pragma unroll
        for (int mi = 0; mi < 4; mi++) {
#pragma unroll
            for (int ni = 0; ni < 8; ni++) {
                int row = r_lo + mi * 16;
                int col = c_lo + ni * 8;
                if (col < N) {
                    atomicAdd(C + (size_t)row * ldc + col, acc[mi][ni][0]);
                    atomicAdd(C + (size_t)(row + 8) * ldc + col, acc[mi][ni][2]);
                }
                if (col + 1 < N) {
                    atomicAdd(C + (size_t)row * ldc + col + 1, acc[mi][ni][1]);
                    atomicAdd(C + (size_t)(row + 8) * ldc + col + 1, acc[mi][ni][3]);
                }
            }
        }
    } else {
#pragma unroll
        for (int mi = 0; mi < 4; mi++) {
#pragma unroll
            for (int ni = 0; ni < 8; ni++) {
                int row = r_lo + mi * 16;
                int col = c_lo + ni * 8;
                float v0 = acc[mi][ni][0], v1 = acc[mi][ni][1];
                float v2 = acc[mi][ni][2], v3 = acc[mi][ni][3];
                if (bias) {
                    float b0 = bias[col], b1 = bias[col + 1];
                    v0 += b0; v1 += b1; v2 += b0; v3 += b1;
                }
                if (act == 1) {
                    v0 = (v0 > 20.f) ? v0 : log1pf(__expf(v0));
                    v1 = (v1 > 20.f) ? v1 : log1pf(__expf(v1));
                    v2 = (v2 > 20.f) ? v2 : log1pf(__expf(v2));
                    v3 = (v3 > 20.f) ? v3 : log1pf(__expf(v3));
                }
                *(float2*)(C + (size_t)row * ldc + col) = make_float2(v0, v1);
                *(float2*)(C + (size_t)(row + 8) * ldc + col) = make_float2(v2, v3);
            }
        }
    }
}

// ---------------- zero buffer ----------------
__global__ void zero1_kernel(float* __restrict__ a, int na)
{
    int idx = blockIdx.x * blockDim.x + threadIdx.x;
    if (idx < na) a[idx] = 0.f;
}

// ---------------- apply text gate; pack gated dt for G3 ----------------
__global__ void gate_apply_kernel()
{
    int idx = blockIdx.x * blockDim.x + threadIdx.x;
    if (idx >= NROWS * NDBL) return;
    int row = idx / NDBL;
    int j = idx - row * NDBL;
    int batch = row >> 10;
    float v = g_xdbl[idx] * g_gate[batch * NDBL + j];
    g_xdbl[idx] = v;
    if (j < DT_RANK) {
        size_t tile = (size_t)(row >> 7) * 2 + (j >> 5);
        g_dt_p[tile * 4096 + inner_a(row & 127, j & 31)] = f2tf32(v);
    }
}

// ---------------- causal depthwise conv (k=4) + SiLU + pack; 4 l per thread --
__global__ void conv_silu_kernel4(const float* __restrict__ conv_w,
                                  const float* __restrict__ conv_b)
{
    int idx = blockIdx.x * blockDim.x + threadIdx.x;
    int total = BATCH * (SEQLEN / 4) * D_INNER;
    if (idx >= total) return;
    int d = idx & (D_INNER - 1);
    int lq = (idx >> 11) & (SEQLEN / 4 - 1);
    int b = idx >> 19;
    int l0 = lq * 4;

    const float* xrow = g_xz + ((size_t)(b * SEQLEN)) * (2 * D_INNER) + d;
    float x[7];
#pragma unroll
    for (int j = 0; j < 7; j++) {
        int l = l0 - 3 + j;
        x[j] = (l >= 0) ? xrow[(size_t)l * (2 * D_INNER)] : 0.f;
    }
    float w0 = conv_w[d * 4 + 0], w1 = conv_w[d * 4 + 1];
    float w2 = conv_w[d * 4 + 2], w3 = conv_w[d * 4 + 3];
    float cb = conv_b[d];

#pragma unroll
    for (int j = 0; j < 4; j++) {
        float acc = cb + x[j] * w0 + x[j + 1] * w1 + x[j + 2] * w2 + x[j + 3] * w3;
        float s = acc / (1.f + __expf(-acc));
        int row = b * SEQLEN + l0 + j;
        g_xc[(size_t)row * D_INNER + d] = s;
        size_t tile = (size_t)(row >> 7) * (D_INNER >> 5) + (d >> 5);
        g_xc_p[tile * 4096 + inner_a(row & 127, d & 31)] = f2tf32(s);
    }
}

// ---------------- text gate ----------------
__global__ void gate_kernel(const float* __restrict__ x_text,
                            const float* __restrict__ gate_w,
                            const float* __restrict__ gate_b)
{
    int t = threadIdx.x;
    if (t >= BATCH * NDBL) return;
    int b = t / NDBL;
    int j = t % NDBL;
    const float* xr = x_text + b * D_MODEL;
    const float* wr = gate_w + (size_t)j * D_MODEL;
    float acc = gate_b[j];
    for (int k = 0; k < D_MODEL; k += 4) {
        float4 xv = *(const float4*)(xr + k);
        float4 wv = *(const float4*)(wr + k);
        acc += xv.x * wv.x + xv.y * wv.y + xv.z * wv.z + xv.w * wv.w;
    }
    g_gate[b * NDBL + j] = 1.f / (1.f + __expf(-acc));
}

// ---------------- fused chunked time-parallel scan ----------------
// CTA = one group of 8 d-values for one b; 256 threads = (chunk c 0..31) x (d_local 0..7).
// Phase 1: per-thread local scan (16 states in regs), He/P -> smem.
// Phase 2: 128 threads walk the 32-chunk prefix in smem (Hin overwrites He).
// Phase 3: per-thread rerun from Hin, fused D*u + silu(z), y packed tf32.
__global__ __launch_bounds__(256) void scan_fused(const float* __restrict__ A_log,
                                                  const float* __restrict__ Dp)
{
    __shared__ float sHeHi[NCHUNK][D_STATE][9];
    __shared__ float sP[NCHUNK][D_STATE][9];

    const int tid = threadIdx.x;
    const int dl_ = tid & 7;
    const int c = tid >> 3;               // 0..31
    const int b = blockIdx.x >> 8;
    const int d = (blockIdx.x & 255) * 8 + dl_;

    float An[D_STATE], h[D_STATE], P[D_STATE];
#pragma unroll
    for (int n = 0; n < D_STATE; n++) {
        An[n] = -__expf(A_log[d * D_STATE + n]);
        h[n] = 0.f;
        P[n] = 1.f;
    }

    const int t0 = c * CLEN;
    const float* dptr = g_delta + ((size_t)(b * SEQLEN + t0)) * D_INNER + d;
    const float* uptr = g_xc + ((size_t)(b * SEQLEN + t0)) * D_INNER + d;
    const float* bc = g_xdbl + ((size_t)(b * SEQLEN + t0)) * NDBL + DT_RANK;

    // ---- phase 1 ----
#pragma unroll 2
    for (int t = 0; t < CLEN; t++) {
        float dl = dptr[(size_t)t * D_INNER];
        float u = uptr[(size_t)t * D_INNER];
        float du = dl * u;
        const float4* b4 = (const float4*)(bc + (size_t)t * NDBL);
        float4 B0 = b4[0], B1 = b4[1], B2 = b4[2], B3 = b4[3];
        float Bv[D_STATE] = {B0.x, B0.y, B0.z, B0.w, B1.x, B1.y, B1.z, B1.w,
                             B2.x, B2.y, B2.z, B2.w, B3.x, B3.y, B3.z, B3.w};
#pragma unroll
        for (int n = 0; n < D_STATE; n++) {
            float a = __expf(dl * An[n]);
            P[n] *= a;
            h[n] = h[n] * a + du * Bv[n];
        }
    }
#pragma unroll
    for (int n = 0; n < D_STATE; n++) {
        sHeHi[c][n][dl_] = h[n];
        sP[c][n][dl_] = P[n];
    }
    __syncthreads();

    // ---- phase 2: chunk prefix (128 threads: d_local x n) ----
    if (tid < 128) {
        int pd = tid >> 4;
        int pn = tid & 15;
        float hr = 0.f;
#pragma unroll
        for (int cc = 0; cc < NCHUNK; cc++) {
            float he = sHeHi[cc][pn][pd];
            float pp = sP[cc][pn][pd];
            sHeHi[cc][pn][pd] = hr;       // now holds Hin
            hr = he + pp * hr;
        }
    }
    __syncthreads();

    // ---- phase 3 ----
#pragma unroll
    for (int n = 0; n < D_STATE; n++) h[n] = sHeHi[c][n][dl_];
    const float Dd = Dp[d];
    const float* zptr = g_xz + ((size_t)(b * SEQLEN + t0)) * (2 * D_INNER) + D_INNER + d;

    const int ik = d & 31;
    const size_t kpart = (size_t)(d >> 5) * 4096 +
                         (ik >> 3) * 128 + (ik & 3) * 4 + ((ik >> 2) & 1) * 2;

#pragma unroll 2
    for (int t = 0; t < CLEN; t++) {
        float dl = dptr[(size_t)t * D_INNER];
        float u = uptr[(size_t)t * D_INNER];
        float z = zptr[(size_t)t * (2 * D_INNER)];
        float du = dl * u;
        const float4* b4 = (const float4*)(bc + (size_t)t * NDBL);
        float4 B0 = b4[0], B1 = b4[1], B2 = b4[2], B3 = b4[3];
        float4 C0 = b4[4], C1 = b4[5], C2 = b4[6], C3 = b4[7];
        float Bv[D_STATE] = {B0.x, B0.y, B0.z, B0.w, B1.x, B1.y, B1.z, B1.w,
                             B2.x, B2.y, B2.z, B2.w, B3.x, B3.y, B3.z, B3.w};
        float Cv[D_STATE] = {C0.x, C0.y, C0.z, C0.w, C1.x, C1.y, C1.z, C1.w,
                             C2.x, C2.y, C2.z, C2.w, C3.x, C3.y, C3.z, C3.w};
        float y0 = 0.f, y1 = 0.f, y2 = 0.f, y3 = 0.f;
#pragma unroll
        for (int n = 0; n < D_STATE; n += 4) {
            float a0 = __expf(dl * An[n + 0]);
            float a1 = __expf(dl * An[n + 1]);
            float a2 = __expf(dl * An[n + 2]);
            float a3 = __expf(dl * An[n + 3]);
            h[n + 0] = h[n + 0] * a0 + du * Bv[n + 0];
            h[n + 1] = h[n + 1] * a1 + du * Bv[n + 1];
            h[n + 2] = h[n + 2] * a2 + du * Bv[n + 2];
            h[n + 3] = h[n + 3] * a3 + du * Bv[n + 3];
            y0 += h[n + 0] * Cv[n + 0];
            y1 += h[n + 1] * Cv[n + 1];
            y2 += h[n + 2] * Cv[n + 2];
            y3 += h[n + 3] * Cv[n + 3];
        }
        float y = (y0 + y1) + (y2 + y3);
        float sz = z / (1.f + __expf(-z));
        float yv = (y + Dd * u) * sz;

        int row = b * SEQLEN + t0 + t;
        int m = row & 127;
        size_t w = (size_t)(row >> 7) * (D_INNER >> 5) * 4096 + kpart +
                   (m >> 4) * 512 + (m & 7) * 16 + ((m >> 3) & 1);
        g_y_p[w] = f2tf32(yv);
    }
}

// ---------------- launcher ----------------
extern "C" void kernel_launch(void* const* d_in, const int* in_sizes, int n_in,
                              void* d_out, int out_size)
{
    const float* hidden    = (const float*)d_in[0];
    const float* x_text    = (const float*)d_in[1];
    const float* in_proj_w = (const float*)d_in[2];
    const float* conv_w    = (const float*)d_in[3];
    const float* conv_b    = (const float*)d_in[4];
    const float* x_proj_w  = (const float*)d_in[5];
    const float* dt_proj_w = (const float*)d_in[6];
    const float* dt_proj_b = (const float*)d_in[7];
    const float* A_log     = (const float*)d_in[8];
    const float* Dp        = (const float*)d_in[9];
    const float* out_proj_w= (const float*)d_in[10];
    const float* gate_w    = (const float*)d_in[11];
    const float* gate_b    = (const float*)d_in[12];
    float* out = (float*)d_out;

    static cudaStream_t s1 = nullptr;
    static cudaEvent_t eFork = nullptr, eJoin1 = nullptr, eJoin2 = nullptr;
    if (!s1) {
        cudaFuncSetAttribute(gemm_mma_p,
                             cudaFuncAttributeMaxDynamicSharedMemorySize, 98304);
        cudaStreamCreateWithFlags(&s1, cudaStreamNonBlocking);
        cudaEventCreateWithFlags(&eFork, cudaEventDisableTiming);
        cudaEventCreateWithFlags(&eJoin1, cudaEventDisableTiming);
        cudaEventCreateWithFlags(&eJoin2, cudaEventDisableTiming);
    }

    float *xz, *xdbl, *delta;
    uint32_t *hid_p, *w1_p, *xc_p, *w2_p, *dt_p, *w3_p, *y_p, *w4_p;
    cudaGetSymbolAddress((void**)&xz, g_xz);
    cudaGetSymbolAddress((void**)&xdbl, g_xdbl);
    cudaGetSymbolAddress((void**)&delta, g_delta);
    cudaGetSymbolAddress((void**)&hid_p, g_hid_p);
    cudaGetSymbolAddress((void**)&w1_p, g_w1_p);
    cudaGetSymbolAddress((void**)&xc_p, g_xc_p);
    cudaGetSymbolAddress((void**)&w2_p, g_w2_p);
    cudaGetSymbolAddress((void**)&dt_p, g_dt_p);
    cudaGetSymbolAddress((void**)&w3_p, g_w3_p);
    cudaGetSymbolAddress((void**)&y_p, g_y_p);
    cudaGetSymbolAddress((void**)&w4_p, g_w4_p);

    const size_t SMEM = 98304;
    // z-half of packed w1: 16 N-tiles * 32 K-tiles * 4096 words
    uint32_t* w1z_p = w1_p + (size_t)16 * 32 * 4096;
    const float* in_proj_w_z = in_proj_w + (size_t)D_INNER * D_MODEL;

    // Fork side stream off the capture origin.
    cudaEventRecord(eFork, 0);
    cudaStreamWaitEvent(s1, eFork, 0);

    // main #1, #2: packs for G1x
    pack_a_t<<<dim3(D_MODEL / 32, NROWS / 128), 256>>>(hidden, hid_p, D_MODEL);
    pack_b_t<<<dim3(D_MODEL / 32, D_INNER / 128), 256>>>(in_proj_w, w1_p,
                                                         D_INNER, D_MODEL);
    // side #3: gate (tiny)
    gate_kernel<<<1, 192, 0, s1>>>(x_text, gate_w, gate_b);

    // main #4 (profiled): G1x — x half: xz[:, 0:2048]
    {
        dim3 grid(D_INNER / 128, NROWS / 128, 1);
        gemm_mma_p<<<grid, 128, SMEM>>>(hid_p, w1_p, xz, 2 * D_INNER,
                                        D_MODEL / 32, D_MODEL / 32, D_INNER,
                                        nullptr, 0, 0);
    }

    // side: early G2/G3 prerequisites, then join1
    pack_b_t<<<dim3(D_INNER / 32, 1), 256, 0, s1>>>(x_proj_w, w2_p, NDBL, D_INNER);
    pack_b_t<<<dim3(DT_RANK / 32, D_INNER / 128), 256, 0, s1>>>(dt_proj_w, w3_p,
                                                                D_INNER, DT_RANK);
    zero1_kernel<<<(NROWS * NDBL + 255) / 256, 256, 0, s1>>>(xdbl, NROWS * NDBL);
    cudaEventRecord(eJoin1, s1);
    // side: z-half pack + G1z + w4 pack, then join2
    pack_b_t<<<dim3(D_MODEL / 32, D_INNER / 128), 256, 0, s1>>>(in_proj_w_z, w1z_p,
                                                                D_INNER, D_MODEL);
    {
        dim3 grid(D_INNER / 128, NROWS / 128, 1);
        gemm_mma_p<<<grid, 128, SMEM, s1>>>(hid_p, w1z_p, xz + D_INNER, 2 * D_INNER,
                                            D_MODEL / 32, D_MODEL / 32, D_INNER,
                                            nullptr, 0, 0);
    }
    pack_b_t<<<dim3(D_INNER / 32, D_MODEL / 128), 256, 0, s1>>>(out_proj_w, w4_p,
                                                                D_MODEL, D_INNER);
    cudaEventRecord(eJoin2, s1);

    // main: conv + silu (+ fused pack of xc); needs only x half
    {
        int total = BATCH * (SEQLEN / 4) * D_INNER;
        conv_silu_kernel4<<<(total + 255) / 256, 256>>>(conv_w, conv_b);
    }

    // join1: w2/w3 packs + xdbl zero ready
    cudaStreamWaitEvent(0, eJoin1, 0);

    // G2: x_dbl = xc @ x_proj_w^T  (2048 x 96, K=2048) split-K=8, atomic
    {
        dim3 grid(1, NROWS / 128, 8);
        gemm_mma_p<<<grid, 128, SMEM>>>(xc_p, w2_p, xdbl, NDBL,
                                        D_INNER / 32, (D_INNER / 32) / 8, NDBL,
                                        nullptr, 0, 1);
    }
    // apply text gate (+ pack gated dt)
    gate_apply_kernel<<<(NROWS * NDBL + 255) / 256, 256>>>();
    // G3: delta = softplus(dt @ dt_proj_w^T + dt_proj_b)
    {
        dim3 grid(D_INNER / 128, NROWS / 128, 1);
        gemm_mma_p<<<grid, 128, SMEM>>>(dt_p, w3_p, delta, D_INNER,
                                        DT_RANK / 32, DT_RANK / 32, D_INNER,
                                        dt_proj_b, 1, 0);
    }
    // join2: z half (G1z) + w4 pack ready (scan phase 3 reads z)
    cudaStreamWaitEvent(0, eJoin2, 0);
    // fused chunked scan (writes y packed)
    scan_fused<<<BATCH * (D_INNER / 8), 256>>>(A_log, Dp);
    // G4: out = y @ out_proj_w^T  (2048 x 1024, K=2048), direct store
    {
        dim3 grid(D_MODEL / 128, NROWS / 128, 1);
        gemm_mma_p<<<grid, 128, SMEM>>>(y_p, w4_p, out, D_MODEL,
                                        D_INNER / 32, D_INNER / 32, D_MODEL,
                                        nullptr, 0, 0);
    }
}

// round 15
// speedup vs baseline: 1.5030x; 1.5030x over previous
#include <cuda_runtime.h>
#include <cuda_bf16.h>
#include <cstdint>

// Problem constants
#define D_MODEL 1024
#define D_INNER 2048
#define D_STATE 16
#define D_CONV  4
#define DT_RANK 64
#define BATCH   2
#define SEQLEN  1024
#define NROWS   (BATCH * SEQLEN)          // 2048 "M" rows
#define NDBL    (DT_RANK + 2 * D_STATE)   // 96
#define NCHUNK  32
#define CLEN    32                        // SEQLEN / NCHUNK

// ---------------- scratch (device globals; no allocation) ----------------
__device__ float g_xz[(size_t)NROWS * 2 * D_INNER];     // (2048, 4096) x|z
__device__ float g_xc[(size_t)NROWS * D_INNER];         // (2048, 2048) conv+silu
__device__ float g_xdbl[(size_t)NROWS * NDBL];          // (2048, 96) dt|B|C
__device__ float g_gate[BATCH * NDBL];                  // (2, 96)
__device__ float g_delta[(size_t)NROWS * D_INNER];      // (2048, 2048)

// chunked-scan intermediates
__device__ float g_P[(size_t)BATCH * D_INNER * NCHUNK * D_STATE];
__device__ float g_He[(size_t)BATCH * D_INNER * NCHUNK * D_STATE];
__device__ float g_Hi[(size_t)BATCH * D_INNER * NCHUNK * D_STATE];

// packed tf32 operand tiles: [tileM(or N)/128][K/32][4096 words]
__device__ uint32_t g_hid_p[(size_t)NROWS * D_MODEL];            // A of G1
__device__ uint32_t g_w1_p[(size_t)2 * D_INNER * D_MODEL];       // B of G1
__device__ uint32_t g_xc_p[(size_t)NROWS * D_INNER];             // A of G2
__device__ uint32_t g_w2_p[(size_t)128 * D_INNER];               // B of G2 (pad 96->128)
__device__ uint32_t g_dt_p[(size_t)NROWS * DT_RANK];             // A of G3
__device__ uint32_t g_w3_p[(size_t)D_INNER * DT_RANK];           // B of G3
__device__ uint32_t g_y_p[(size_t)NROWS * D_INNER];              // A of G4
__device__ uint32_t g_w4_p[(size_t)D_MODEL * D_INNER];           // B of G4

// ---------------- helpers ----------------
__device__ __forceinline__ uint32_t f2tf32(float x) {
    uint32_t r;
    asm("cvt.rna.tf32.f32 %0, %1;" : "=r"(r) : "f"(x));
    return r;
}

__device__ __forceinline__ uint32_t smem_u32(const void* p) {
    uint32_t a;
    asm("{ .reg .u64 t; cvta.to.shared.u64 t, %1; cvt.u32.u64 %0, t; }"
        : "=r"(a) : "l"(p));
    return a;
}

__device__ __forceinline__ void mma_tf32(float c[4], const uint32_t a[4],
                                         const uint32_t b[2]) {
    asm volatile(
        "mma.sync.aligned.m16n8k8.row.col.f32.tf32.tf32.f32 "
        "{%0,%1,%2,%3}, {%4,%5,%6,%7}, {%8,%9}, {%0,%1,%2,%3};"
        : "+f"(c[0]), "+f"(c[1]), "+f"(c[2]), "+f"(c[3])
        : "r"(a[0]), "r"(a[1]), "r"(a[2]), "r"(a[3]), "r"(b[0]), "r"(b[1]));
}

#define CP16(dst, src) \
    asm volatile("cp.async.cg.shared.global [%0], [%1], 16;" \
                 :: "r"(dst), "l"(src) : "memory")

// fragment-packed word index within a 128x32 A tile (4096 words)
__device__ __forceinline__ int inner_a(int m, int k) {
    return ((m >> 4) * 4 + (k >> 3)) * 128 + (m & 7) * 16 + (k & 3) * 4 +
           ((k >> 2) & 1) * 2 + ((m >> 3) & 1);
}

// ---------------- coalesced pack kernels (smem-inverse; block = one tile) ---
__global__ __launch_bounds__(256) void pack_a_t(const float* __restrict__ src,
                                                uint32_t* __restrict__ dst, int K)
{
    __shared__ float s[128][33];
    const int tid = threadIdx.x;
    const int k0 = blockIdx.x * 32;
    const int row0 = blockIdx.y * 128;
    const int r = tid >> 1;
    const int cb = (tid & 1) * 16;
    const float* sp = src + (size_t)(row0 + r) * K + k0 + cb;
#pragma unroll
    for (int p = 0; p < 4; p++) {
        float4 v = *(const float4*)(sp + p * 4);
        s[r][cb + p * 4 + 0] = v.x; s[r][cb + p * 4 + 1] = v.y;
        s[r][cb + p * 4 + 2] = v.z; s[r][cb + p * 4 + 3] = v.w;
    }
    __syncthreads();
    uint32_t* dp = dst + ((size_t)blockIdx.y * gridDim.x + blockIdx.x) * 4096 + tid * 16;
#pragma unroll
    for (int q = 0; q < 4; q++) {
        uint4 o;
        uint32_t* po = (uint32_t*)&o;
#pragma unroll
        for (int w = 0; w < 4; w++) {
            int g = tid * 16 + q * 4 + w;
            int f = g >> 7, i = g & 127;
            int m = ((f >> 2) << 4) | ((i & 1) << 3) | (i >> 4);
            int k = ((f & 3) << 3) | (((i >> 1) & 1) << 2) | ((i >> 2) & 3);
            po[w] = f2tf32(s[m][k]);
        }
        *(uint4*)(dp + q * 4) = o;
    }
}

__global__ __launch_bounds__(256) void pack_b_t(const float* __restrict__ src,
                                                uint32_t* __restrict__ dst,
                                                int N, int K)
{
    __shared__ float s[128][33];
    const int tid = threadIdx.x;
    const int k0 = blockIdx.x * 32;
    const int n0 = blockIdx.y * 128;
    const int r = tid >> 1;
    const int cb = (tid & 1) * 16;
    const int gn = n0 + r;
    const float* sp = src + (size_t)gn * K + k0 + cb;
#pragma unroll
    for (int p = 0; p < 4; p++) {
        float4 v = (gn < N) ? *(const float4*)(sp + p * 4)
                            : make_float4(0.f, 0.f, 0.f, 0.f);
        s[r][cb + p * 4 + 0] = v.x; s[r][cb + p * 4 + 1] = v.y;
        s[r][cb + p * 4 + 2] = v.z; s[r][cb + p * 4 + 3] = v.w;
    }
    __syncthreads();
    uint32_t* dp = dst + ((size_t)blockIdx.y * gridDim.x + blockIdx.x) * 4096 + tid * 16;
#pragma unroll
    for (int q = 0; q < 4; q++) {
        uint4 o;
        uint32_t* po = (uint32_t*)&o;
#pragma unroll
        for (int w = 0; w < 4; w++) {
            int g = tid * 16 + q * 4 + w;
            int f = g >> 6, i = g & 63;
            int n = ((f >> 2) << 3) | (i >> 3);
            int k = ((f & 3) << 3) | ((i & 1) << 2) | ((i >> 1) & 3);
            po[w] = f2tf32(s[n][k]);
        }
        *(uint4*)(dp + q * 4) = o;
    }
}

// ---------------- 3-stage pipelined tensor-core tf32 GEMM ----------------
__global__ __launch_bounds__(128)
void gemm_mma_p(const uint32_t* __restrict__ Ap,
                const uint32_t* __restrict__ Bp,
                float* __restrict__ C, int ldc,
                int nKtiles, int ktCnt, int N,
                const float* __restrict__ bias, int act, int atomic)
{
    extern __shared__ uint32_t smem[];   // 3 * 8192 words = 96 KB

    const int tid = threadIdx.x;
    const int wid = tid >> 5;
    const int lane = tid & 31;
    const int warp_m = wid >> 1;
    const int warp_n = wid & 1;
    const int ktBeg = blockIdx.z * ktCnt;

    const uint32_t* gA = Ap + ((size_t)blockIdx.y * nKtiles + ktBeg) * 4096;
    const uint32_t* gB = Bp + ((size_t)blockIdx.x * nKtiles + ktBeg) * 4096;
    const uint32_t sbase = smem_u32(smem);

    float acc[4][8][4];
#pragma unroll
    for (int mi = 0; mi < 4; mi++)
#pragma unroll
        for (int ni = 0; ni < 8; ni++)
#pragma unroll
            for (int e = 0; e < 4; e++) acc[mi][ni][e] = 0.f;

#define ISSUE_STAGE(s) do { \
    int _buf = (s) % 3; \
    uint32_t _d = sbase + _buf * 32768 + tid * 16; \
    const char* _sA = (const char*)(gA + (size_t)(s) * 4096) + tid * 16; \
    const char* _sB = (const char*)(gB + (size_t)(s) * 4096) + tid * 16; \
    _Pragma("unroll") \
    for (int _i = 0; _i < 8; _i++) { \
        CP16(_d + _i * 2048, _sA + _i * 2048); \
        CP16(_d + 16384 + _i * 2048, _sB + _i * 2048); \
    } \
    asm volatile("cp.async.commit_group;" ::: "memory"); \
} while (0)

    ISSUE_STAGE(0);
    ISSUE_STAGE(1);                       // ktCnt >= 2 for all callers
    for (int s = 0; s < ktCnt; s++) {
        if (s + 1 < ktCnt) {
            asm volatile("cp.async.wait_group 1;" ::: "memory");
        } else {
            asm volatile("cp.async.wait_group 0;" ::: "memory");
        }
        __syncthreads();

        const uint32_t* sA = smem + (s % 3) * 8192;
        const uint32_t* sB = sA + 4096;
#pragma unroll
        for (int kc = 0; kc < 4; kc++) {
            uint4 af[4];
            uint2 bf[8];
#pragma unroll
            for (int mi = 0; mi < 4; mi++)
                af[mi] = *(const uint4*)&sA[((warp_m * 4 + mi) * 4 + kc) * 128 + lane * 4];
#pragma unroll
            for (int ni = 0; ni < 8; ni++)
                bf[ni] = *(const uint2*)&sB[((warp_n * 8 + ni) * 4 + kc) * 64 + lane * 2];
#pragma unroll
            for (int mi = 0; mi < 4; mi++)
#pragma unroll
                for (int ni = 0; ni < 8; ni++)
                    mma_tf32(acc[mi][ni], (const uint32_t*)&af[mi],
                             (const uint32_t*)&bf[ni]);
        }
        if (s + 2 < ktCnt) ISSUE_STAGE(s + 2);
    }
#undef ISSUE_STAGE

    const int r_lo = blockIdx.y * 128 + warp_m * 64 + (lane >> 2);
    const int c_lo = blockIdx.x * 128 + warp_n * 64 + (lane & 3) * 2;
    if (atomic) {
#pragma unroll
        for (int mi = 0; mi < 4; mi++) {
#pragma unroll
            for (int ni = 0; ni < 8; ni++) {
                int row = r_lo + mi * 16;
                int col = c_lo + ni * 8;
                if (col < N) {
                    atomicAdd(C + (size_t)row * ldc + col, acc[mi][ni][0]);
                    atomicAdd(C + (size_t)(row + 8) * ldc + col, acc[mi][ni][2]);
                }
                if (col + 1 < N) {
                    atomicAdd(C + (size_t)row * ldc + col + 1, acc[mi][ni][1]);
                    atomicAdd(C + (size_t)(row + 8) * ldc + col + 1, acc[mi][ni][3]);
                }
            }
        }
    } else {
#pragma unroll
        for (int mi = 0; mi < 4; mi++) {
#pragma unroll
            for (int ni = 0; ni < 8; ni++) {
                int row = r_lo + mi * 16;
                int col = c_lo + ni * 8;
                float v0 = acc[mi][ni][0], v1 = acc[mi][ni][1];
                float v2 = acc[mi][ni][2], v3 = acc[mi][ni][3];
                if (bias) {
                    float b0 = bias[col], b1 = bias[col + 1];
                    v0 += b0; v1 += b1; v2 += b0; v3 += b1;
                }
                if (act == 1) {
                    v0 = (v0 > 20.f) ? v0 : log1pf(__expf(v0));
                    v1 = (v1 > 20.f) ? v1 : log1pf(__expf(v1));
                    v2 = (v2 > 20.f) ? v2 : log1pf(__expf(v2));
                    v3 = (v3 > 20.f) ? v3 : log1pf(__expf(v3));
                }
                *(float2*)(C + (size_t)row * ldc + col) = make_float2(v0, v1);
                *(float2*)(C + (size_t)(row + 8) * ldc + col) = make_float2(v2, v3);
            }
        }
    }
}

// ---------------- zero buffer ----------------
__global__ void zero1_kernel(float* __restrict__ a, int na)
{
    int idx = blockIdx.x * blockDim.x + threadIdx.x;
    if (idx < na) a[idx] = 0.f;
}

// ---------------- apply text gate; pack gated dt for G3 ----------------
__global__ void gate_apply_kernel()
{
    int idx = blockIdx.x * blockDim.x + threadIdx.x;
    if (idx >= NROWS * NDBL) return;
    int row = idx / NDBL;
    int j = idx - row * NDBL;
    int batch = row >> 10;
    float v = g_xdbl[idx] * g_gate[batch * NDBL + j];
    g_xdbl[idx] = v;
    if (j < DT_RANK) {
        size_t tile = (size_t)(row >> 7) * 2 + (j >> 5);
        g_dt_p[tile * 4096 + inner_a(row & 127, j & 31)] = f2tf32(v);
    }
}

// ---------------- causal depthwise conv (k=4) + SiLU + pack; 4 l per thread --
__global__ void conv_silu_kernel4(const float* __restrict__ conv_w,
                                  const float* __restrict__ conv_b)
{
    int idx = blockIdx.x * blockDim.x + threadIdx.x;
    int total = BATCH * (SEQLEN / 4) * D_INNER;
    if (idx >= total) return;
    int d = idx & (D_INNER - 1);
    int lq = (idx >> 11) & (SEQLEN / 4 - 1);
    int b = idx >> 19;
    int l0 = lq * 4;

    const float* xrow = g_xz + ((size_t)(b * SEQLEN)) * (2 * D_INNER) + d;
    float x[7];
#pragma unroll
    for (int j = 0; j < 7; j++) {
        int l = l0 - 3 + j;
        x[j] = (l >= 0) ? xrow[(size_t)l * (2 * D_INNER)] : 0.f;
    }
    float w0 = conv_w[d * 4 + 0], w1 = conv_w[d * 4 + 1];
    float w2 = conv_w[d * 4 + 2], w3 = conv_w[d * 4 + 3];
    float cb = conv_b[d];

#pragma unroll
    for (int j = 0; j < 4; j++) {
        float acc = cb + x[j] * w0 + x[j + 1] * w1 + x[j + 2] * w2 + x[j + 3] * w3;
        float s = acc / (1.f + __expf(-acc));
        int row = b * SEQLEN + l0 + j;
        g_xc[(size_t)row * D_INNER + d] = s;
        size_t tile = (size_t)(row >> 7) * (D_INNER >> 5) + (d >> 5);
        g_xc_p[tile * 4096 + inner_a(row & 127, d & 31)] = f2tf32(s);
    }
}

// ---------------- text gate ----------------
__global__ void gate_kernel(const float* __restrict__ x_text,
                            const float* __restrict__ gate_w,
                            const float* __restrict__ gate_b)
{
    int t = threadIdx.x;
    if (t >= BATCH * NDBL) return;
    int b = t / NDBL;
    int j = t % NDBL;
    const float* xr = x_text + b * D_MODEL;
    const float* wr = gate_w + (size_t)j * D_MODEL;
    float acc = gate_b[j];
    for (int k = 0; k < D_MODEL; k += 4) {
        float4 xv = *(const float4*)(xr + k);
        float4 wv = *(const float4*)(wr + k);
        acc += xv.x * wv.x + xv.y * wv.y + xv.z * wv.z + xv.w * wv.w;
    }
    g_gate[b * NDBL + j] = 1.f / (1.f + __expf(-acc));
}

// ---------------- chunked time-parallel scan (three-pass, R13 form) --------
__global__ __launch_bounds__(256) void scan_pass1(const float* __restrict__ A_log)
{
    int idx = blockIdx.x * blockDim.x + threadIdx.x;   // 131072
    int d = idx & (D_INNER - 1);
    int c = (idx >> 11) & (NCHUNK - 1);
    int b = idx >> 16;

    float An[D_STATE], h[D_STATE], P[D_STATE];
#pragma unroll
    for (int n = 0; n < D_STATE; n++) {
        An[n] = -__expf(A_log[d * D_STATE + n]);
        h[n] = 0.f;
        P[n] = 1.f;
    }

    const int t0 = c * CLEN;
    const float* dptr = g_delta + ((size_t)(b * SEQLEN + t0)) * D_INNER + d;
    const float* uptr = g_xc + ((size_t)(b * SEQLEN + t0)) * D_INNER + d;
    const float* bc = g_xdbl + ((size_t)(b * SEQLEN + t0)) * NDBL + DT_RANK;

#pragma unroll 2
    for (int t = 0; t < CLEN; t++) {
        float dl = dptr[(size_t)t * D_INNER];
        float u = uptr[(size_t)t * D_INNER];
        float du = dl * u;
        const float4* b4 = (const float4*)(bc + (size_t)t * NDBL);
        float4 B0 = b4[0], B1 = b4[1], B2 = b4[2], B3 = b4[3];
        float Bv[D_STATE] = {B0.x, B0.y, B0.z, B0.w, B1.x, B1.y, B1.z, B1.w,
                             B2.x, B2.y, B2.z, B2.w, B3.x, B3.y, B3.z, B3.w};
#pragma unroll
        for (int n = 0; n < D_STATE; n++) {
            float a = __expf(dl * An[n]);
            P[n] *= a;
            h[n] = h[n] * a + du * Bv[n];
        }
    }

    float* pp = g_P + ((size_t)((b * D_INNER + d) * NCHUNK + c)) * D_STATE;
    float* hp = g_He + ((size_t)((b * D_INNER + d) * NCHUNK + c)) * D_STATE;
#pragma unroll
    for (int q = 0; q < 4; q++) {
        *(float4*)(pp + q * 4) = make_float4(P[q*4], P[q*4+1], P[q*4+2], P[q*4+3]);
        *(float4*)(hp + q * 4) = make_float4(h[q*4], h[q*4+1], h[q*4+2], h[q*4+3]);
    }
}

__global__ __launch_bounds__(256) void scan_pass2()
{
    int idx = blockIdx.x * blockDim.x + threadIdx.x;   // 65536
    int n = idx & (D_STATE - 1);
    int d = (idx >> 4) & (D_INNER - 1);
    int b = idx >> 15;
    size_t base = ((size_t)(b * D_INNER + d) * NCHUNK) * D_STATE + n;
    float h = 0.f;
#pragma unroll
    for (int c = 0; c < NCHUNK; c++) {
        g_Hi[base + (size_t)c * D_STATE] = h;
        h = g_He[base + (size_t)c * D_STATE] + g_P[base + (size_t)c * D_STATE] * h;
    }
}

__global__ __launch_bounds__(256) void scan_pass3(const float* __restrict__ A_log,
                                                  const float* __restrict__ Dp)
{
    int idx = blockIdx.x * blockDim.x + threadIdx.x;   // 131072
    int d = idx & (D_INNER - 1);
    int c = (idx >> 11) & (NCHUNK - 1);
    int b = idx >> 16;

    float An[D_STATE], h[D_STATE];
#pragma unroll
    for (int n = 0; n < D_STATE; n++)
        An[n] = -__expf(A_log[d * D_STATE + n]);
    {
        const float* hi = g_Hi + ((size_t)((b * D_INNER + d) * NCHUNK + c)) * D_STATE;
#pragma unroll
        for (int q = 0; q < 4; q++) {
            float4 v = *(const float4*)(hi + q * 4);
            h[q*4] = v.x; h[q*4+1] = v.y; h[q*4+2] = v.z; h[q*4+3] = v.w;
        }
    }
    const float Dd = Dp[d];

    const int t0 = c * CLEN;
    const float* dptr = g_delta + ((size_t)(b * SEQLEN + t0)) * D_INNER + d;
    const float* uptr = g_xc + ((size_t)(b * SEQLEN + t0)) * D_INNER + d;
    const float* bc = g_xdbl + ((size_t)(b * SEQLEN + t0)) * NDBL + DT_RANK;
    const float* zptr = g_xz + ((size_t)(b * SEQLEN + t0)) * (2 * D_INNER) + D_INNER + d;

    const int ik = d & 31;
    const size_t kpart = (size_t)(d >> 5) * 4096 +
                         (ik >> 3) * 128 + (ik & 3) * 4 + ((ik >> 2) & 1) * 2;

#pragma unroll 2
    for (int t = 0; t < CLEN; t++) {
        float dl = dptr[(size_t)t * D_INNER];
        float u = uptr[(size_t)t * D_INNER];
        float z = zptr[(size_t)t * (2 * D_INNER)];
        float du = dl * u;
        const float4* b4 = (const float4*)(bc + (size_t)t * NDBL);
        float4 B0 = b4[0], B1 = b4[1], B2 = b4[2], B3 = b4[3];
        float4 C0 = b4[4], C1 = b4[5], C2 = b4[6], C3 = b4[7];
        float Bv[D_STATE] = {B0.x, B0.y, B0.z, B0.w, B1.x, B1.y, B1.z, B1.w,
                             B2.x, B2.y, B2.z, B2.w, B3.x, B3.y, B3.z, B3.w};
        float Cv[D_STATE] = {C0.x, C0.y, C0.z, C0.w, C1.x, C1.y, C1.z, C1.w,
                             C2.x, C2.y, C2.z, C2.w, C3.x, C3.y, C3.z, C3.w};
        float y0 = 0.f, y1 = 0.f, y2 = 0.f, y3 = 0.f;
#pragma unroll
        for (int n = 0; n < D_STATE; n += 4) {
            float a0 = __expf(dl * An[n + 0]);
            float a1 = __expf(dl * An[n + 1]);
            float a2 = __expf(dl * An[n + 2]);
            float a3 = __expf(dl * An[n + 3]);
            h[n + 0] = h[n + 0] * a0 + du * Bv[n + 0];
            h[n + 1] = h[n + 1] * a1 + du * Bv[n + 1];
            h[n + 2] = h[n + 2] * a2 + du * Bv[n + 2];
            h[n + 3] = h[n + 3] * a3 + du * Bv[n + 3];
            y0 += h[n + 0] * Cv[n + 0];
            y1 += h[n + 1] * Cv[n + 1];
            y2 += h[n + 2] * Cv[n + 2];
            y3 += h[n + 3] * Cv[n + 3];
        }
        float y = (y0 + y1) + (y2 + y3);
        float sz = z / (1.f + __expf(-z));
        float yv = (y + Dd * u) * sz;

        int row = b * SEQLEN + t0 + t;
        int m = row & 127;
        size_t w = (size_t)(row >> 7) * (D_INNER >> 5) * 4096 + kpart +
                   (m >> 4) * 512 + (m & 7) * 16 + ((m >> 3) & 1);
        g_y_p[w] = f2tf32(yv);
    }
}

// ---------------- launcher ----------------
extern "C" void kernel_launch(void* const* d_in, const int* in_sizes, int n_in,
                              void* d_out, int out_size)
{
    const float* hidden    = (const float*)d_in[0];
    const float* x_text    = (const float*)d_in[1];
    const float* in_proj_w = (const float*)d_in[2];
    const float* conv_w    = (const float*)d_in[3];
    const float* conv_b    = (const float*)d_in[4];
    const float* x_proj_w  = (const float*)d_in[5];
    const float* dt_proj_w = (const float*)d_in[6];
    const float* dt_proj_b = (const float*)d_in[7];
    const float* A_log     = (const float*)d_in[8];
    const float* Dp        = (const float*)d_in[9];
    const float* out_proj_w= (const float*)d_in[10];
    const float* gate_w    = (const float*)d_in[11];
    const float* gate_b    = (const float*)d_in[12];
    float* out = (float*)d_out;

    static cudaStream_t s1 = nullptr;
    static cudaEvent_t eFork = nullptr, eJoin1 = nullptr, eJoin2 = nullptr;
    if (!s1) {
        cudaFuncSetAttribute(gemm_mma_p,
                             cudaFuncAttributeMaxDynamicSharedMemorySize, 98304);
        cudaStreamCreateWithFlags(&s1, cudaStreamNonBlocking);
        cudaEventCreateWithFlags(&eFork, cudaEventDisableTiming);
        cudaEventCreateWithFlags(&eJoin1, cudaEventDisableTiming);
        cudaEventCreateWithFlags(&eJoin2, cudaEventDisableTiming);
    }

    float *xz, *xdbl, *delta;
    uint32_t *hid_p, *w1_p, *xc_p, *w2_p, *dt_p, *w3_p, *y_p, *w4_p;
    cudaGetSymbolAddress((void**)&xz, g_xz);
    cudaGetSymbolAddress((void**)&xdbl, g_xdbl);
    cudaGetSymbolAddress((void**)&delta, g_delta);
    cudaGetSymbolAddress((void**)&hid_p, g_hid_p);
    cudaGetSymbolAddress((void**)&w1_p, g_w1_p);
    cudaGetSymbolAddress((void**)&xc_p, g_xc_p);
    cudaGetSymbolAddress((void**)&w2_p, g_w2_p);
    cudaGetSymbolAddress((void**)&dt_p, g_dt_p);
    cudaGetSymbolAddress((void**)&w3_p, g_w3_p);
    cudaGetSymbolAddress((void**)&y_p, g_y_p);
    cudaGetSymbolAddress((void**)&w4_p, g_w4_p);

    const size_t SMEM = 98304;
    // z-half of packed w1: 16 N-tiles * 32 K-tiles * 4096 words
    uint32_t* w1z_p = w1_p + (size_t)16 * 32 * 4096;
    const float* in_proj_w_z = in_proj_w + (size_t)D_INNER * D_MODEL;

    // Fork side stream off the capture origin.
    cudaEventRecord(eFork, 0);
    cudaStreamWaitEvent(s1, eFork, 0);

    // main #1, #2: packs for G1x
    pack_a_t<<<dim3(D_MODEL / 32, NROWS / 128), 256>>>(hidden, hid_p, D_MODEL);
    pack_b_t<<<dim3(D_MODEL / 32, D_INNER / 128), 256>>>(in_proj_w, w1_p,
                                                         D_INNER, D_MODEL);
    // side #3: gate (tiny)
    gate_kernel<<<1, 192, 0, s1>>>(x_text, gate_w, gate_b);

    // main #4 (profiled): G1x — x half: xz[:, 0:2048]
    {
        dim3 grid(D_INNER / 128, NROWS / 128, 1);
        gemm_mma_p<<<grid, 128, SMEM>>>(hid_p, w1_p, xz, 2 * D_INNER,
                                        D_MODEL / 32, D_MODEL / 32, D_INNER,
                                        nullptr, 0, 0);
    }

    // side: early G2/G3 prerequisites, then join1
    pack_b_t<<<dim3(D_INNER / 32, 1), 256, 0, s1>>>(x_proj_w, w2_p, NDBL, D_INNER);
    pack_b_t<<<dim3(DT_RANK / 32, D_INNER / 128), 256, 0, s1>>>(dt_proj_w, w3_p,
                                                                D_INNER, DT_RANK);
    zero1_kernel<<<(NROWS * NDBL + 255) / 256, 256, 0, s1>>>(xdbl, NROWS * NDBL);
    cudaEventRecord(eJoin1, s1);
    // side: z-half pack + G1z + w4 pack, then join2
    pack_b_t<<<dim3(D_MODEL / 32, D_INNER / 128), 256, 0, s1>>>(in_proj_w_z, w1z_p,
                                                                D_INNER, D_MODEL);
    {
        dim3 grid(D_INNER / 128, NROWS / 128, 1);
        gemm_mma_p<<<grid, 128, SMEM, s1>>>(hid_p, w1z_p, xz + D_INNER, 2 * D_INNER,
                                            D_MODEL / 32, D_MODEL / 32, D_INNER,
                                            nullptr, 0, 0);
    }
    pack_b_t<<<dim3(D_INNER / 32, D_MODEL / 128), 256, 0, s1>>>(out_proj_w, w4_p,
                                                                D_MODEL, D_INNER);
    cudaEventRecord(eJoin2, s1);

    // main: conv + silu (+ fused pack of xc); needs only x half
    {
        int total = BATCH * (SEQLEN / 4) * D_INNER;
        conv_silu_kernel4<<<(total + 255) / 256, 256>>>(conv_w, conv_b);
    }

    // join1: w2/w3 packs + xdbl zero ready
    cudaStreamWaitEvent(0, eJoin1, 0);

    // G2: x_dbl = xc @ x_proj_w^T  (2048 x 96, K=2048) split-K=8, atomic
    {
        dim3 grid(1, NROWS / 128, 8);
        gemm_mma_p<<<grid, 128, SMEM>>>(xc_p, w2_p, xdbl, NDBL,
                                        D_INNER / 32, (D_INNER / 32) / 8, NDBL,
                                        nullptr, 0, 1);
    }
    // apply text gate (+ pack gated dt)
    gate_apply_kernel<<<(NROWS * NDBL + 255) / 256, 256>>>();
    // G3: delta = softplus(dt @ dt_proj_w^T + dt_proj_b)
    {
        dim3 grid(D_INNER / 128, NROWS / 128, 1);
        gemm_mma_p<<<grid, 128, SMEM>>>(dt_p, w3_p, delta, D_INNER,
                                        DT_RANK / 32, DT_RANK / 32, D_INNER,
                                        dt_proj_b, 1, 0);
    }
    // scan passes 1-2 (independent of z half)
    scan_pass1<<<512, 256>>>(A_log);
    scan_pass2<<<256, 256>>>();
    // join2: z half (G1z) + w4 pack ready
    cudaStreamWaitEvent(0, eJoin2, 0);
    scan_pass3<<<512, 256>>>(A_log, Dp);
    // G4: out = y @ out_proj_w^T  (2048 x 1024, K=2048), direct store
    {
        dim3 grid(D_MODEL / 128, NROWS / 128, 1);
        gemm_mma_p<<<grid, 128, SMEM>>>(y_p, w4_p, out, D_MODEL,
                                        D_INNER / 32, D_INNER / 32, D_MODEL,
                                        nullptr, 0, 0);
    }
}